// round 7
// baseline (speedup 1.0000x reference)
#include <cuda_runtime.h>

#define HID 64
typedef unsigned long long u64;

__device__ __forceinline__ u64 pk2(float lo, float hi) {
    u64 r; asm("mov.b64 %0, {%1,%2};" : "=l"(r) : "f"(lo), "f"(hi)); return r;
}
__device__ __forceinline__ void upk2(u64 v, float& lo, float& hi) {
    asm("mov.b64 {%0,%1}, %2;" : "=f"(lo), "=f"(hi) : "l"(v));
}
__device__ __forceinline__ u64 ffma2(u64 a, u64 b, u64 c) {
    u64 d; asm("fma.rn.f32x2 %0, %1, %2, %3;" : "=l"(d) : "l"(a), "l"(b), "l"(c)); return d;
}

// Packed weight blocks, h-pair interleaved. Per family: 32 h2-blocks of 16 u64:
//   s in [0,DIN)      : (W1[s,2h2], W1[s,2h2+1])
//   s == DIN          : (b1[2h2],  b1[2h2+1])
//   s in (DIN,DIN+9]  : (W2[2h2,m], W2[2h2+1,m])
// plus 9 trailing (b2[m], 0) pairs at offset 512.
#define FAMWORDS (16 * 32 + 9)
__constant__ u64 cWB[3][FAMWORDS];
__device__   u64 g_scratch[3][FAMWORDS];

__global__ void zero_kernel(float* __restrict__ out, int n) {
    int i = blockIdx.x * blockDim.x + threadIdx.x;
    if (i < n) out[i] = 0.0f;
}

__global__ void prepack_kernel(
    const float* __restrict__ W1_2b, const float* __restrict__ b1_2b,
    const float* __restrict__ W2_2b, const float* __restrict__ b2_2b,
    const float* __restrict__ W1_3b, const float* __restrict__ b1_3b,
    const float* __restrict__ W2_3b, const float* __restrict__ b2_3b,
    const float* __restrict__ W1_s,  const float* __restrict__ b1_s,
    const float* __restrict__ W2_s,  const float* __restrict__ b2_s)
{
    int idx = blockIdx.x * blockDim.x + threadIdx.x;
    int total = 3 * FAMWORDS;
    for (; idx < total; idx += gridDim.x * blockDim.x) {
        int f = idx / FAMWORDS;
        int r = idx - f * FAMWORDS;
        int DIN = (f == 1) ? 6 : 3;
        const float* W1 = (f == 0) ? W1_2b : (f == 1) ? W1_3b : W1_s;
        const float* b1 = (f == 0) ? b1_2b : (f == 1) ? b1_3b : b1_s;
        const float* W2 = (f == 0) ? W2_2b : (f == 1) ? W2_3b : W2_s;
        const float* b2 = (f == 0) ? b2_2b : (f == 1) ? b2_3b : b2_s;
        float lo = 0.0f, hi = 0.0f;
        if (r < 512) {
            int h2 = r >> 4, s = r & 15;
            int h0 = 2 * h2, h1 = h0 + 1;
            if (s < DIN)           { lo = W1[s * HID + h0]; hi = W1[s * HID + h1]; }
            else if (s == DIN)     { lo = b1[h0];           hi = b1[h1]; }
            else if (s <= DIN + 9) { int m = s - DIN - 1; lo = W2[h0 * 9 + m]; hi = W2[h1 * 9 + m]; }
        } else {
            lo = b2[r - 512];   // (b2, 0): seeded into even-h lane only
        }
        g_scratch[f][r] = pk2(lo, hi);
    }
}

// FAM selects the __constant__ bank at compile time -> const-space loads
// (LDCU/LDC on the constant port; zero smem, zero weight GPR pressure).
template<int FAM, int DIN, int EPT>
__device__ __forceinline__ void run_family(
    const float* __restrict__ x,
    const int*   __restrict__ edges,
    const float* __restrict__ attr,
    float* __restrict__ out, int E, int blk, int nblk)
{
    const int tid    = blk * (int)blockDim.x + (int)threadIdx.x;
    const int stride = nblk * (int)blockDim.x;

    u64  dd[EPT][DIN];
    u64  acc[EPT][9];
    int  tgt[EPT];
    bool valid[EPT];

    #pragma unroll
    for (int k = 0; k < EPT; k++) {
        int e = tid + k * stride;
        valid[k] = (e < E);
        int ee = valid[k] ? e : 0;
        float dv[DIN];
        int i;
        if (DIN == 3) {
            int j = edges[ee];
            i = edges[E + ee];
            dv[0] = x[3*j+0] - x[3*i+0];
            dv[1] = x[3*j+1] - x[3*i+1];
            dv[2] = x[3*j+2] - x[3*i+2];
        } else {
            int j  = edges[ee];
            int kk = edges[E + ee];
            i = edges[2*E + ee];
            float xk0 = x[3*kk+0], xk1 = x[3*kk+1], xk2 = x[3*kk+2];
            dv[0] = xk0 - x[3*j+0];
            dv[1] = xk1 - x[3*j+1];
            dv[2] = xk2 - x[3*j+2];
            dv[3] = x[3*i+0] - xk0;
            dv[4] = x[3*i+1] - xk1;
            dv[5] = x[3*i+2] - xk2;
        }
        tgt[k] = i;
        #pragma unroll
        for (int q = 0; q < DIN; q++) dd[k][q] = pk2(dv[q], dv[q]);
        #pragma unroll
        for (int m = 0; m < 9; m++) acc[k][m] = cWB[FAM][512 + m];
    }

    // Mainloop: 32 h-pair iterations; weights from the constant port.
    #pragma unroll 4
    for (int h2 = 0; h2 < 32; h2++) {
        const int base = h2 * 16;

        u64 hv[EPT];
        #pragma unroll
        for (int k = 0; k < EPT; k++) {
            u64 t = cWB[FAM][base + DIN];               // b1 pair
            #pragma unroll
            for (int i = 0; i < DIN; i++)
                t = ffma2(dd[k][i], cWB[FAM][base + i], t);
            float lo, hi; upk2(t, lo, hi);
            lo = fmaxf(lo, 0.0f); hi = fmaxf(hi, 0.0f);
            hv[k] = pk2(lo, hi);
        }

        #pragma unroll
        for (int m = 0; m < 9; m++) {
            u64 w = cWB[FAM][base + DIN + 1 + m];
            #pragma unroll
            for (int k = 0; k < EPT; k++)
                acc[k][m] = ffma2(hv[k], w, acc[k][m]);
        }
    }

    // Epilogue: merge h-lanes, matvec with attr, scatter-add.
    #pragma unroll
    for (int k = 0; k < EPT; k++) {
        if (!valid[k]) continue;
        int e = tid + k * stride;
        float a0 = attr[3*e+0], a1 = attr[3*e+1], a2v = attr[3*e+2];
        #pragma unroll
        for (int i = 0; i < 3; i++) {
            float m0lo, m0hi, m1lo, m1hi, m2lo, m2hi;
            upk2(acc[k][3*i+0], m0lo, m0hi);
            upk2(acc[k][3*i+1], m1lo, m1hi);
            upk2(acc[k][3*i+2], m2lo, m2hi);
            float y = fmaf(m0lo + m0hi, a0,
                      fmaf(m1lo + m1hi, a1,
                           (m2lo + m2hi) * a2v));
            atomicAdd(&out[3*tgt[k] + i], y);
        }
    }
}

#define EPT3B 4
#define EPT6B 2

__global__ __launch_bounds__(128, 4)
void fused_hignn_kernel(
    const float* __restrict__ x,
    const int* __restrict__ e2, const float* __restrict__ a2,
    const int* __restrict__ e3, const float* __restrict__ a3,
    const int* __restrict__ es, const float* __restrict__ as,
    float* __restrict__ out,
    int E2, int E3, int ES, int B2, int B3, int BS)
{
    int b = blockIdx.x;
    if (b < B2) {
        run_family<0, 3, EPT3B>(x, e2, a2, out, E2, b, B2);
    } else if (b < B2 + B3) {
        run_family<1, 6, EPT6B>(x, e3, a3, out, E3, b - B2, B3);
    } else {
        run_family<2, 3, EPT3B>(x, es, as, out, ES, b - B2 - B3, BS);
    }
}

extern "C" void kernel_launch(void* const* d_in, const int* in_sizes, int n_in,
                              void* d_out, int out_size)
{
    const float* x   = (const float*)d_in[0];
    const int*   e2  = (const int*)  d_in[1];
    const int*   e3  = (const int*)  d_in[2];
    const int*   es  = (const int*)  d_in[3];
    const float* a2  = (const float*)d_in[5];
    const float* a3  = (const float*)d_in[6];
    const float* as  = (const float*)d_in[7];
    const float* W1_2b = (const float*)d_in[9];
    const float* b1_2b = (const float*)d_in[10];
    const float* W2_2b = (const float*)d_in[11];
    const float* b2_2b = (const float*)d_in[12];
    const float* W1_3b = (const float*)d_in[13];
    const float* b1_3b = (const float*)d_in[14];
    const float* W2_3b = (const float*)d_in[15];
    const float* b2_3b = (const float*)d_in[16];
    const float* W1_s  = (const float*)d_in[17];
    const float* b1_s  = (const float*)d_in[18];
    const float* W2_s  = (const float*)d_in[19];
    const float* b2_s  = (const float*)d_in[20];

    const int E2 = in_sizes[1] / 2;
    const int E3 = in_sizes[2] / 3;
    const int ES = in_sizes[3] / 2;

    float* out = (float*)d_out;

    // 1) prepack weights into h-pair layout (device scratch)
    prepack_kernel<<<13, 128>>>(W1_2b, b1_2b, W2_2b, b2_2b,
                                W1_3b, b1_3b, W2_3b, b2_3b,
                                W1_s,  b1_s,  W2_s,  b2_s);

    // 2) move packed weights into __constant__ (D2D async memcpy; capturable)
    void* scratch_addr = nullptr;
    void* const_addr   = nullptr;
    cudaGetSymbolAddress(&scratch_addr, g_scratch);
    cudaGetSymbolAddress(&const_addr, cWB);
    cudaMemcpyAsync(const_addr, scratch_addr, sizeof(u64) * 3 * FAMWORDS,
                    cudaMemcpyDeviceToDevice);

    // 3) zero output
    zero_kernel<<<(out_size + 255) / 256, 256>>>(out, out_size);

    // 4) fused edge kernel
    constexpr int BLK = 128;
    const int B2 = (E2 + EPT3B * BLK - 1) / (EPT3B * BLK);
    const int B3 = (E3 + EPT6B * BLK - 1) / (EPT6B * BLK);
    const int BS = (ES + EPT3B * BLK - 1) / (EPT3B * BLK);

    fused_hignn_kernel<<<B2 + B3 + BS, BLK>>>(
        x, e2, a2, e3, a3, es, as, out, E2, E3, ES, B2, B3, BS);
}

// round 8
// speedup vs baseline: 1.0976x; 1.0976x over previous
#include <cuda_runtime.h>

#define HID 64
typedef unsigned long long u64;

__device__ __forceinline__ u64 pk2(float lo, float hi) {
    u64 r; asm("mov.b64 %0, {%1,%2};" : "=l"(r) : "f"(lo), "f"(hi)); return r;
}
__device__ __forceinline__ void upk2(u64 v, float& lo, float& hi) {
    asm("mov.b64 {%0,%1}, %2;" : "=f"(lo), "=f"(hi) : "l"(v));
}
__device__ __forceinline__ u64 ffma2(u64 a, u64 b, u64 c) {
    u64 d; asm("fma.rn.f32x2 %0, %1, %2, %3;" : "=l"(d) : "l"(a), "l"(b), "l"(c)); return d;
}

__global__ void zero_kernel(float* __restrict__ out, int n) {
    int i = blockIdx.x * blockDim.x + threadIdx.x;
    if (i < n) out[i] = 0.0f;
}

// h-PAIR packed scheme, fused dispatch, JIT weight loads (low reg pressure).
// Weight block per h2 (stride NW = DIN+1+9 u64):
//   [0,DIN) : (W1[s,2h2], W1[s,2h2+1]);  DIN : (b1 pair);  (DIN,NW) : W2 pairs
// Accumulators packed (even-h lane0, odd-h lane1), merged in epilogue.
// W2 pairs loaded JUST-IN-TIME per output column: live weight window ~2 u64.
template<int DIN, int EPT>
__device__ __forceinline__ void run_family(
    const float* __restrict__ x,
    const int*   __restrict__ edges,
    const float* __restrict__ attr,
    const float* __restrict__ W1, const float* __restrict__ b1,
    const float* __restrict__ W2, const float* __restrict__ b2,
    float* __restrict__ out, int E, int blk, int nblk, u64* smem)
{
    constexpr int NW = DIN + 1 + 9;
    u64* sWB = smem;              // [NW * 32]
    u64* sB2 = sWB + NW * 32;     // [9]

    for (int idx = threadIdx.x; idx < NW * 32; idx += blockDim.x) {
        int h2 = idx / NW, s = idx - h2 * NW;
        int h0 = 2 * h2, h1 = 2 * h2 + 1;
        float lo, hi;
        if (s < DIN)       { lo = W1[s * HID + h0]; hi = W1[s * HID + h1]; }
        else if (s == DIN) { lo = b1[h0];           hi = b1[h1]; }
        else               { int m = s - DIN - 1; lo = W2[h0 * 9 + m]; hi = W2[h1 * 9 + m]; }
        sWB[idx] = pk2(lo, hi);
    }
    if (threadIdx.x < 9) sB2[threadIdx.x] = pk2(b2[threadIdx.x], 0.0f);
    __syncthreads();

    const int tid    = blk * (int)blockDim.x + (int)threadIdx.x;
    const int stride = nblk * (int)blockDim.x;

    u64  dd[EPT][DIN];     // (d,d) duplicated MLP inputs
    u64  acc[EPT][9];      // packed accumulators (even-h lane0, odd-h lane1)
    int  tgt[EPT];
    bool valid[EPT];

    #pragma unroll
    for (int k = 0; k < EPT; k++) {
        int e = tid + k * stride;
        valid[k] = (e < E);
        int ee = valid[k] ? e : 0;
        float dv[DIN];
        int i;
        if (DIN == 3) {
            int j = edges[ee];
            i = edges[E + ee];
            dv[0] = x[3*j+0] - x[3*i+0];
            dv[1] = x[3*j+1] - x[3*i+1];
            dv[2] = x[3*j+2] - x[3*i+2];
        } else {
            int j  = edges[ee];
            int kk = edges[E + ee];
            i = edges[2*E + ee];
            float xk0 = x[3*kk+0], xk1 = x[3*kk+1], xk2 = x[3*kk+2];
            dv[0] = xk0 - x[3*j+0];
            dv[1] = xk1 - x[3*j+1];
            dv[2] = xk2 - x[3*j+2];
            dv[3] = x[3*i+0] - xk0;
            dv[4] = x[3*i+1] - xk1;
            dv[5] = x[3*i+2] - xk2;
        }
        tgt[k] = i;
        #pragma unroll
        for (int q = 0; q < DIN; q++) dd[k][q] = pk2(dv[q], dv[q]);
        #pragma unroll
        for (int m = 0; m < 9; m++) acc[k][m] = sB2[m];
    }

    // Mainloop: 32 h-pair iterations. Layer-1 weights up front (DIN+1 u64 live),
    // W2 pairs loaded just-in-time per output column (live window ~2 u64).
    #pragma unroll 2
    for (int h2 = 0; h2 < 32; h2++) {
        const u64* wp = sWB + h2 * NW;

        u64 w1p[DIN];
        #pragma unroll
        for (int i = 0; i < DIN; i++) w1p[i] = wp[i];
        u64 bh = wp[DIN];

        u64 hv[EPT];
        #pragma unroll
        for (int k = 0; k < EPT; k++) {
            u64 t = bh;
            #pragma unroll
            for (int i = 0; i < DIN; i++) t = ffma2(dd[k][i], w1p[i], t);
            float lo, hi; upk2(t, lo, hi);
            lo = fmaxf(lo, 0.0f); hi = fmaxf(hi, 0.0f);
            hv[k] = pk2(lo, hi);
        }

        #pragma unroll
        for (int m = 0; m < 9; m++) {
            u64 w = wp[DIN + 1 + m];        // JIT load: short live range
            #pragma unroll
            for (int k = 0; k < EPT; k++)
                acc[k][m] = ffma2(hv[k], w, acc[k][m]);
        }
    }

    // Epilogue: merge h-lanes, matvec with attr, scatter-add.
    #pragma unroll
    for (int k = 0; k < EPT; k++) {
        if (!valid[k]) continue;
        int e = tid + k * stride;
        float a0 = attr[3*e+0], a1 = attr[3*e+1], a2v = attr[3*e+2];
        #pragma unroll
        for (int i = 0; i < 3; i++) {
            float m0lo, m0hi, m1lo, m1hi, m2lo, m2hi;
            upk2(acc[k][3*i+0], m0lo, m0hi);
            upk2(acc[k][3*i+1], m1lo, m1hi);
            upk2(acc[k][3*i+2], m2lo, m2hi);
            float y = fmaf(m0lo + m0hi, a0,
                      fmaf(m1lo + m1hi, a1,
                           (m2lo + m2hi) * a2v));
            atomicAdd(&out[3*tgt[k] + i], y);
        }
    }
}

#define EPT3B 4   // DIN=3 families
#define EPT6B 3   // DIN=6 family

__global__ __launch_bounds__(128)
void fused_hignn_kernel(
    const float* __restrict__ x,
    const int* __restrict__ e2, const float* __restrict__ a2,
    const float* __restrict__ W1_2b, const float* __restrict__ b1_2b,
    const float* __restrict__ W2_2b, const float* __restrict__ b2_2b,
    const int* __restrict__ e3, const float* __restrict__ a3,
    const float* __restrict__ W1_3b, const float* __restrict__ b1_3b,
    const float* __restrict__ W2_3b, const float* __restrict__ b2_3b,
    const int* __restrict__ es, const float* __restrict__ as,
    const float* __restrict__ W1_s, const float* __restrict__ b1_s,
    const float* __restrict__ W2_s, const float* __restrict__ b2_s,
    float* __restrict__ out,
    int E2, int E3, int ES, int B2, int B3, int BS)
{
    __shared__ __align__(16) u64 smem[16 * 32 + 9];
    int b = blockIdx.x;
    if (b < B2) {
        run_family<3, EPT3B>(x, e2, a2, W1_2b, b1_2b, W2_2b, b2_2b, out, E2, b, B2, smem);
    } else if (b < B2 + B3) {
        run_family<6, EPT6B>(x, e3, a3, W1_3b, b1_3b, W2_3b, b2_3b, out, E3, b - B2, B3, smem);
    } else {
        run_family<3, EPT3B>(x, es, as, W1_s, b1_s, W2_s, b2_s, out, ES, b - B2 - B3, BS, smem);
    }
}

extern "C" void kernel_launch(void* const* d_in, const int* in_sizes, int n_in,
                              void* d_out, int out_size)
{
    const float* x   = (const float*)d_in[0];
    const int*   e2  = (const int*)  d_in[1];
    const int*   e3  = (const int*)  d_in[2];
    const int*   es  = (const int*)  d_in[3];
    const float* a2  = (const float*)d_in[5];
    const float* a3  = (const float*)d_in[6];
    const float* as  = (const float*)d_in[7];
    const float* W1_2b = (const float*)d_in[9];
    const float* b1_2b = (const float*)d_in[10];
    const float* W2_2b = (const float*)d_in[11];
    const float* b2_2b = (const float*)d_in[12];
    const float* W1_3b = (const float*)d_in[13];
    const float* b1_3b = (const float*)d_in[14];
    const float* W2_3b = (const float*)d_in[15];
    const float* b2_3b = (const float*)d_in[16];
    const float* W1_s  = (const float*)d_in[17];
    const float* b1_s  = (const float*)d_in[18];
    const float* W2_s  = (const float*)d_in[19];
    const float* b2_s  = (const float*)d_in[20];

    const int E2 = in_sizes[1] / 2;
    const int E3 = in_sizes[2] / 3;
    const int ES = in_sizes[3] / 2;

    float* out = (float*)d_out;

    zero_kernel<<<(out_size + 255) / 256, 256>>>(out, out_size);

    constexpr int BLK = 128;
    const int B2 = (E2 + EPT3B * BLK - 1) / (EPT3B * BLK);
    const int B3 = (E3 + EPT6B * BLK - 1) / (EPT6B * BLK);
    const int BS = (ES + EPT3B * BLK - 1) / (EPT3B * BLK);

    fused_hignn_kernel<<<B2 + B3 + BS, BLK>>>(
        x,
        e2, a2, W1_2b, b1_2b, W2_2b, b2_2b,
        e3, a3, W1_3b, b1_3b, W2_3b, b2_3b,
        es, as, W1_s, b1_s, W2_s, b2_s,
        out, E2, E3, ES, B2, B3, BS);
}

// round 9
// speedup vs baseline: 1.1535x; 1.0509x over previous
#include <cuda_runtime.h>

#define HID 64
typedef unsigned long long u64;

__device__ __forceinline__ u64 pk2(float lo, float hi) {
    u64 r; asm("mov.b64 %0, {%1,%2};" : "=l"(r) : "f"(lo), "f"(hi)); return r;
}
__device__ __forceinline__ void upk2(u64 v, float& lo, float& hi) {
    asm("mov.b64 {%0,%1}, %2;" : "=f"(lo), "=f"(hi) : "l"(v));
}
__device__ __forceinline__ u64 ffma2(u64 a, u64 b, u64 c) {
    u64 d; asm("fma.rn.f32x2 %0, %1, %2, %3;" : "=l"(d) : "l"(a), "l"(b), "l"(c)); return d;
}

__global__ void zero_kernel(float* __restrict__ out, int n) {
    int i = blockIdx.x * blockDim.x + threadIdx.x;
    if (i < n) out[i] = 0.0f;
}

// h-PAIR packed weights, 16-u64 (128B, float4-aligned) block per h2:
//   pair s in [0,DIN)     : (W1[s,2h2], W1[s,2h2+1])
//   pair DIN              : (b1[2h2], b1[2h2+1])
//   pair DIN+1 .. DIN+9   : (W2[2h2,m], W2[2h2+1,m])
// Mainloop reads blocks as float4 (LDS.128): 7 loads per h2 instead of 13
// LDS.64. Layer-1 is scalar (d stored as floats, halves of each float4 are
// the even/odd-h weights); layer-2 uses FFMA2 with register-pair aliased
// packed weights. Accumulators packed (even-h lane0 / odd-h lane1).
template<int DIN, int EPT>
__device__ __forceinline__ void run_family(
    const float* __restrict__ x,
    const int*   __restrict__ edges,
    const float* __restrict__ attr,
    const float* __restrict__ W1, const float* __restrict__ b1,
    const float* __restrict__ W2, const float* __restrict__ b2,
    float* __restrict__ out, int E, int blk, int nblk, u64* smem)
{
    u64* sWB = smem;              // [16 * 32]
    u64* sB2 = sWB + 16 * 32;     // [9]

    for (int idx = threadIdx.x; idx < 16 * 32; idx += blockDim.x) {
        int h2 = idx >> 4, s = idx & 15;
        int h0 = 2 * h2, h1 = 2 * h2 + 1;
        float lo = 0.0f, hi = 0.0f;
        if (s < DIN)           { lo = W1[s * HID + h0]; hi = W1[s * HID + h1]; }
        else if (s == DIN)     { lo = b1[h0];           hi = b1[h1]; }
        else if (s <= DIN + 9) { int m = s - DIN - 1; lo = W2[h0 * 9 + m]; hi = W2[h1 * 9 + m]; }
        sWB[idx] = pk2(lo, hi);
    }
    if (threadIdx.x < 9) sB2[threadIdx.x] = pk2(b2[threadIdx.x], 0.0f);
    __syncthreads();

    const int tid    = blk * (int)blockDim.x + (int)threadIdx.x;
    const int stride = nblk * (int)blockDim.x;

    float dv[EPT][DIN];    // scalar MLP inputs
    u64   acc[EPT][9];     // packed accumulators (even-h lane0, odd-h lane1)
    int   tgt[EPT];
    bool  valid[EPT];

    #pragma unroll
    for (int k = 0; k < EPT; k++) {
        int e = tid + k * stride;
        valid[k] = (e < E);
        int ee = valid[k] ? e : 0;
        int i;
        if (DIN == 3) {
            int j = edges[ee];
            i = edges[E + ee];
            dv[k][0] = x[3*j+0] - x[3*i+0];
            dv[k][1] = x[3*j+1] - x[3*i+1];
            dv[k][2] = x[3*j+2] - x[3*i+2];
        } else {
            int j  = edges[ee];
            int kk = edges[E + ee];
            i = edges[2*E + ee];
            float xk0 = x[3*kk+0], xk1 = x[3*kk+1], xk2 = x[3*kk+2];
            dv[k][0] = xk0 - x[3*j+0];
            dv[k][1] = xk1 - x[3*j+1];
            dv[k][2] = xk2 - x[3*j+2];
            dv[k][3] = x[3*i+0] - xk0;
            dv[k][4] = x[3*i+1] - xk1;
            dv[k][5] = x[3*i+2] - xk2;
        }
        tgt[k] = i;
        #pragma unroll
        for (int m = 0; m < 9; m++) acc[k][m] = sB2[m];
    }

    // Mainloop: 32 h-pair iterations, 7 (DIN3) / 8 (DIN6) LDS.128 each.
    #pragma unroll 2
    for (int h2 = 0; h2 < 32; h2++) {
        const float4* w4 = (const float4*)(sWB + h2 * 16);
        u64 hv[EPT];

        if (DIN == 3) {
            float4 qa = w4[0];                 // w1_0 pair, w1_1 pair
            float4 qb = w4[1];                 // w1_2 pair, b1 pair
            #pragma unroll
            for (int k = 0; k < EPT; k++) {
                float t0 = fmaf(dv[k][0], qa.x, qb.z);
                float t1 = fmaf(dv[k][0], qa.y, qb.w);
                t0 = fmaf(dv[k][1], qa.z, t0);
                t1 = fmaf(dv[k][1], qa.w, t1);
                t0 = fmaf(dv[k][2], qb.x, t0);
                t1 = fmaf(dv[k][2], qb.y, t1);
                hv[k] = pk2(fmaxf(t0, 0.0f), fmaxf(t1, 0.0f));
            }
            // layer-2 pairs 4..12 -> float4 idx 2..6 (JIT, short live range)
            #pragma unroll
            for (int g = 0; g < 5; g++) {
                float4 q = w4[2 + g];
                u64 wA = pk2(q.x, q.y);
                #pragma unroll
                for (int k = 0; k < EPT; k++)
                    acc[k][2*g+0] = ffma2(hv[k], wA, acc[k][2*g+0]);
                if (g < 4) {
                    u64 wB = pk2(q.z, q.w);
                    #pragma unroll
                    for (int k = 0; k < EPT; k++)
                        acc[k][2*g+1] = ffma2(hv[k], wB, acc[k][2*g+1]);
                }
            }
        } else {
            float4 qa = w4[0];                 // w1_0, w1_1
            float4 qb = w4[1];                 // w1_2, w1_3
            float4 qc = w4[2];                 // w1_4, w1_5
            float4 qd = w4[3];                 // b1, w2_0
            #pragma unroll
            for (int k = 0; k < EPT; k++) {
                float t0 = fmaf(dv[k][0], qa.x, qd.x);
                float t1 = fmaf(dv[k][0], qa.y, qd.y);
                t0 = fmaf(dv[k][1], qa.z, t0);
                t1 = fmaf(dv[k][1], qa.w, t1);
                t0 = fmaf(dv[k][2], qb.x, t0);
                t1 = fmaf(dv[k][2], qb.y, t1);
                t0 = fmaf(dv[k][3], qb.z, t0);
                t1 = fmaf(dv[k][3], qb.w, t1);
                t0 = fmaf(dv[k][4], qc.x, t0);
                t1 = fmaf(dv[k][4], qc.y, t1);
                t0 = fmaf(dv[k][5], qc.z, t0);
                t1 = fmaf(dv[k][5], qc.w, t1);
                hv[k] = pk2(fmaxf(t0, 0.0f), fmaxf(t1, 0.0f));
            }
            // w2_0 = qd.zw; w2_1..w2_8 = float4 idx 4..7
            {
                u64 w0 = pk2(qd.z, qd.w);
                #pragma unroll
                for (int k = 0; k < EPT; k++)
                    acc[k][0] = ffma2(hv[k], w0, acc[k][0]);
            }
            #pragma unroll
            for (int g = 0; g < 4; g++) {
                float4 q = w4[4 + g];
                u64 wA = pk2(q.x, q.y);
                u64 wB = pk2(q.z, q.w);
                #pragma unroll
                for (int k = 0; k < EPT; k++)
                    acc[k][2*g+1] = ffma2(hv[k], wA, acc[k][2*g+1]);
                #pragma unroll
                for (int k = 0; k < EPT; k++)
                    acc[k][2*g+2] = ffma2(hv[k], wB, acc[k][2*g+2]);
            }
        }
    }

    // Epilogue: merge h-lanes, matvec with attr, scatter-add.
    #pragma unroll
    for (int k = 0; k < EPT; k++) {
        if (!valid[k]) continue;
        int e = tid + k * stride;
        float a0 = attr[3*e+0], a1 = attr[3*e+1], a2v = attr[3*e+2];
        #pragma unroll
        for (int i = 0; i < 3; i++) {
            float m0lo, m0hi, m1lo, m1hi, m2lo, m2hi;
            upk2(acc[k][3*i+0], m0lo, m0hi);
            upk2(acc[k][3*i+1], m1lo, m1hi);
            upk2(acc[k][3*i+2], m2lo, m2hi);
            float y = fmaf(m0lo + m0hi, a0,
                      fmaf(m1lo + m1hi, a1,
                           (m2lo + m2hi) * a2v));
            atomicAdd(&out[3*tgt[k] + i], y);
        }
    }
}

#define EPT3B 4   // DIN=3 families
#define EPT6B 3   // DIN=6 family

__global__ __launch_bounds__(128, 4)
void fused_hignn_kernel(
    const float* __restrict__ x,
    const int* __restrict__ e2, const float* __restrict__ a2,
    const float* __restrict__ W1_2b, const float* __restrict__ b1_2b,
    const float* __restrict__ W2_2b, const float* __restrict__ b2_2b,
    const int* __restrict__ e3, const float* __restrict__ a3,
    const float* __restrict__ W1_3b, const float* __restrict__ b1_3b,
    const float* __restrict__ W2_3b, const float* __restrict__ b2_3b,
    const int* __restrict__ es, const float* __restrict__ as,
    const float* __restrict__ W1_s, const float* __restrict__ b1_s,
    const float* __restrict__ W2_s, const float* __restrict__ b2_s,
    float* __restrict__ out,
    int E2, int E3, int ES, int B2, int B3, int BS)
{
    __shared__ __align__(16) u64 smem[16 * 32 + 9];
    int b = blockIdx.x;
    if (b < B2) {
        run_family<3, EPT3B>(x, e2, a2, W1_2b, b1_2b, W2_2b, b2_2b, out, E2, b, B2, smem);
    } else if (b < B2 + B3) {
        run_family<6, EPT6B>(x, e3, a3, W1_3b, b1_3b, W2_3b, b2_3b, out, E3, b - B2, B3, smem);
    } else {
        run_family<3, EPT3B>(x, es, as, W1_s, b1_s, W2_s, b2_s, out, ES, b - B2 - B3, BS, smem);
    }
}

extern "C" void kernel_launch(void* const* d_in, const int* in_sizes, int n_in,
                              void* d_out, int out_size)
{
    const float* x   = (const float*)d_in[0];
    const int*   e2  = (const int*)  d_in[1];
    const int*   e3  = (const int*)  d_in[2];
    const int*   es  = (const int*)  d_in[3];
    const float* a2  = (const float*)d_in[5];
    const float* a3  = (const float*)d_in[6];
    const float* as  = (const float*)d_in[7];
    const float* W1_2b = (const float*)d_in[9];
    const float* b1_2b = (const float*)d_in[10];
    const float* W2_2b = (const float*)d_in[11];
    const float* b2_2b = (const float*)d_in[12];
    const float* W1_3b = (const float*)d_in[13];
    const float* b1_3b = (const float*)d_in[14];
    const float* W2_3b = (const float*)d_in[15];
    const float* b2_3b = (const float*)d_in[16];
    const float* W1_s  = (const float*)d_in[17];
    const float* b1_s  = (const float*)d_in[18];
    const float* W2_s  = (const float*)d_in[19];
    const float* b2_s  = (const float*)d_in[20];

    const int E2 = in_sizes[1] / 2;
    const int E3 = in_sizes[2] / 3;
    const int ES = in_sizes[3] / 2;

    float* out = (float*)d_out;

    zero_kernel<<<(out_size + 255) / 256, 256>>>(out, out_size);

    constexpr int BLK = 128;
    const int B2 = (E2 + EPT3B * BLK - 1) / (EPT3B * BLK);
    const int B3 = (E3 + EPT6B * BLK - 1) / (EPT6B * BLK);
    const int BS = (ES + EPT3B * BLK - 1) / (EPT3B * BLK);

    fused_hignn_kernel<<<B2 + B3 + BS, BLK>>>(
        x,
        e2, a2, W1_2b, b1_2b, W2_2b, b2_2b,
        e3, a3, W1_3b, b1_3b, W2_3b, b2_3b,
        es, as, W1_s, b1_s, W2_s, b2_s,
        out, E2, E3, ES, B2, B3, BS);
}

// round 11
// speedup vs baseline: 1.1708x; 1.0150x over previous
#include <cuda_runtime.h>

#define HID 64
typedef unsigned long long u64;

__device__ __forceinline__ u64 pk2(float lo, float hi) {
    u64 r; asm("mov.b64 %0, {%1,%2};" : "=l"(r) : "f"(lo), "f"(hi)); return r;
}
__device__ __forceinline__ void upk2(u64 v, float& lo, float& hi) {
    asm("mov.b64 {%0,%1}, %2;" : "=f"(lo), "=f"(hi) : "l"(v));
}
__device__ __forceinline__ u64 ffma2(u64 a, u64 b, u64 c) {
    u64 d; asm("fma.rn.f32x2 %0, %1, %2, %3;" : "=l"(d) : "l"(a), "l"(b), "l"(c)); return d;
}
__device__ __forceinline__ u64 fmul2(u64 a, u64 b) {
    u64 d; asm("mul.rn.f32x2 %0, %1, %2;" : "=l"(d) : "l"(a), "l"(b)); return d;
}

__global__ void zero_kernel(float* __restrict__ out, int n) {
    int i = blockIdx.x * blockDim.x + threadIdx.x;
    if (i < n) out[i] = 0.0f;
}

// h-PAIR packed weights (16-u64 / 128B float4-aligned block per h2) with
// attr FOLDED INTO LAYER 2:
//   y_i = sum_m b2[3i+m] at_m  +  sum_h hv_h * (sum_m W2[h][3i+m] at_m)
// Per edge only THREE packed accumulators (even-h lane0 / odd-h lane1) are
// carried, instead of nine mobility entries -> big register savings ->
// 5 blocks/SM. attr is held duplicated (at,at) for FFMA2 with h-pair weights.
template<int DIN, int EPT>
__device__ __forceinline__ void run_family(
    const float* __restrict__ x,
    const int*   __restrict__ edges,
    const float* __restrict__ attr,
    const float* __restrict__ W1, const float* __restrict__ b1,
    const float* __restrict__ W2, const float* __restrict__ b2,
    float* __restrict__ out, int E, int blk, int nblk, u64* smem)
{
    u64*   sWB = smem;                      // [16 * 32]
    float* sB2 = (float*)(sWB + 16 * 32);   // [9]

    for (int idx = threadIdx.x; idx < 16 * 32; idx += blockDim.x) {
        int h2 = idx >> 4, s = idx & 15;
        int h0 = 2 * h2, h1 = 2 * h2 + 1;
        float lo = 0.0f, hi = 0.0f;
        if (s < DIN)           { lo = W1[s * HID + h0]; hi = W1[s * HID + h1]; }
        else if (s == DIN)     { lo = b1[h0];           hi = b1[h1]; }
        else if (s <= DIN + 9) { int m = s - DIN - 1; lo = W2[h0 * 9 + m]; hi = W2[h1 * 9 + m]; }
        sWB[idx] = pk2(lo, hi);
    }
    if (threadIdx.x < 9) sB2[threadIdx.x] = b2[threadIdx.x];
    __syncthreads();

    const int tid    = blk * (int)blockDim.x + (int)threadIdx.x;
    const int stride = nblk * (int)blockDim.x;

    float dv[EPT][DIN];    // scalar MLP inputs
    u64   atd[EPT][3];     // (at_m, at_m) duplicated attrs
    u64   acc[EPT][3];     // packed y accumulators (even-h lane0, odd-h lane1)
    int   tgt[EPT];
    bool  valid[EPT];

    #pragma unroll
    for (int k = 0; k < EPT; k++) {
        int e = tid + k * stride;
        valid[k] = (e < E);
        int ee = valid[k] ? e : 0;
        int i;
        if (DIN == 3) {
            int j = edges[ee];
            i = edges[E + ee];
            dv[k][0] = x[3*j+0] - x[3*i+0];
            dv[k][1] = x[3*j+1] - x[3*i+1];
            dv[k][2] = x[3*j+2] - x[3*i+2];
        } else {
            int j  = edges[ee];
            int kk = edges[E + ee];
            i = edges[2*E + ee];
            float xk0 = x[3*kk+0], xk1 = x[3*kk+1], xk2 = x[3*kk+2];
            dv[k][0] = xk0 - x[3*j+0];
            dv[k][1] = xk1 - x[3*j+1];
            dv[k][2] = xk2 - x[3*j+2];
            dv[k][3] = x[3*i+0] - xk0;
            dv[k][4] = x[3*i+1] - xk1;
            dv[k][5] = x[3*i+2] - xk2;
        }
        tgt[k] = i;
        float a0 = attr[3*ee+0], a1 = attr[3*ee+1], a2v = attr[3*ee+2];
        atd[k][0] = pk2(a0, a0);
        atd[k][1] = pk2(a1, a1);
        atd[k][2] = pk2(a2v, a2v);
        // seed with b2 . attr (even-h lane)
        #pragma unroll
        for (int i2 = 0; i2 < 3; i2++) {
            float s0 = fmaf(sB2[3*i2+0], a0,
                       fmaf(sB2[3*i2+1], a1, sB2[3*i2+2] * a2v));
            acc[k][i2] = pk2(s0, 0.0f);
        }
    }

    // Mainloop: 32 h-pair iterations.
    #pragma unroll 2
    for (int h2 = 0; h2 < 32; h2++) {
        const float4* w4 = (const float4*)(sWB + h2 * 16);
        u64 hv[EPT];
        u64 w2p[9];

        if (DIN == 3) {
            float4 qa = w4[0];                 // w1_0 pair, w1_1 pair
            float4 qb = w4[1];                 // w1_2 pair, b1 pair
            #pragma unroll
            for (int k = 0; k < EPT; k++) {
                float t0 = fmaf(dv[k][0], qa.x, qb.z);
                float t1 = fmaf(dv[k][0], qa.y, qb.w);
                t0 = fmaf(dv[k][1], qa.z, t0);
                t1 = fmaf(dv[k][1], qa.w, t1);
                t0 = fmaf(dv[k][2], qb.x, t0);
                t1 = fmaf(dv[k][2], qb.y, t1);
                hv[k] = pk2(fmaxf(t0, 0.0f), fmaxf(t1, 0.0f));
            }
            float4 q2 = w4[2], q3 = w4[3], q4 = w4[4], q5 = w4[5], q6 = w4[6];
            w2p[0] = pk2(q2.x, q2.y); w2p[1] = pk2(q2.z, q2.w);
            w2p[2] = pk2(q3.x, q3.y); w2p[3] = pk2(q3.z, q3.w);
            w2p[4] = pk2(q4.x, q4.y); w2p[5] = pk2(q4.z, q4.w);
            w2p[6] = pk2(q5.x, q5.y); w2p[7] = pk2(q5.z, q5.w);
            w2p[8] = pk2(q6.x, q6.y);
        } else {
            float4 qa = w4[0], qb = w4[1], qc = w4[2], qd = w4[3];
            #pragma unroll
            for (int k = 0; k < EPT; k++) {
                float t0 = fmaf(dv[k][0], qa.x, qd.x);
                float t1 = fmaf(dv[k][0], qa.y, qd.y);
                t0 = fmaf(dv[k][1], qa.z, t0);
                t1 = fmaf(dv[k][1], qa.w, t1);
                t0 = fmaf(dv[k][2], qb.x, t0);
                t1 = fmaf(dv[k][2], qb.y, t1);
                t0 = fmaf(dv[k][3], qb.z, t0);
                t1 = fmaf(dv[k][3], qb.w, t1);
                t0 = fmaf(dv[k][4], qc.x, t0);
                t1 = fmaf(dv[k][4], qc.y, t1);
                t0 = fmaf(dv[k][5], qc.z, t0);
                t1 = fmaf(dv[k][5], qc.w, t1);
                hv[k] = pk2(fmaxf(t0, 0.0f), fmaxf(t1, 0.0f));
            }
            float4 q4 = w4[4], q5 = w4[5], q6 = w4[6], q7 = w4[7];
            w2p[0] = pk2(qd.z, qd.w);
            w2p[1] = pk2(q4.x, q4.y); w2p[2] = pk2(q4.z, q4.w);
            w2p[3] = pk2(q5.x, q5.y); w2p[4] = pk2(q5.z, q5.w);
            w2p[5] = pk2(q6.x, q6.y); w2p[6] = pk2(q6.z, q6.w);
            w2p[7] = pk2(q7.x, q7.y); w2p[8] = pk2(q7.z, q7.w);
        }

        // Layer 2 with attr folded: tmp_i = sum_m w2p[3i+m] (.) atd_m ;
        // acc_i += hv (.) tmp_i
        #pragma unroll
        for (int k = 0; k < EPT; k++) {
            #pragma unroll
            for (int i = 0; i < 3; i++) {
                u64 t = fmul2(w2p[3*i+2], atd[k][2]);
                t = ffma2(w2p[3*i+1], atd[k][1], t);
                t = ffma2(w2p[3*i+0], atd[k][0], t);
                acc[k][i] = ffma2(hv[k], t, acc[k][i]);
            }
        }
    }

    // Epilogue: y_i = lane0 + lane1, scatter-add.
    #pragma unroll
    for (int k = 0; k < EPT; k++) {
        if (!valid[k]) continue;
        #pragma unroll
        for (int i = 0; i < 3; i++) {
            float lo, hi; upk2(acc[k][i], lo, hi);
            atomicAdd(&out[3*tgt[k] + i], lo + hi);
        }
    }
}

#define EPT3B 4   // DIN=3 families
#define EPT6B 3   // DIN=6 family

__global__ __launch_bounds__(128, 5)
void fused_hignn_kernel(
    const float* __restrict__ x,
    const int* __restrict__ e2, const float* __restrict__ a2,
    const float* __restrict__ W1_2b, const float* __restrict__ b1_2b,
    const float* __restrict__ W2_2b, const float* __restrict__ b2_2b,
    const int* __restrict__ e3, const float* __restrict__ a3,
    const float* __restrict__ W1_3b, const float* __restrict__ b1_3b,
    const float* __restrict__ W2_3b, const float* __restrict__ b2_3b,
    const int* __restrict__ es, const float* __restrict__ as,
    const float* __restrict__ W1_s, const float* __restrict__ b1_s,
    const float* __restrict__ W2_s, const float* __restrict__ b2_s,
    float* __restrict__ out,
    int E2, int E3, int ES, int B2, int B3, int BS)
{
    __shared__ __align__(16) u64 smem[16 * 32 + 8];
    int b = blockIdx.x;
    if (b < B2) {
        run_family<3, EPT3B>(x, e2, a2, W1_2b, b1_2b, W2_2b, b2_2b, out, E2, b, B2, smem);
    } else if (b < B2 + B3) {
        run_family<6, EPT6B>(x, e3, a3, W1_3b, b1_3b, W2_3b, b2_3b, out, E3, b - B2, B3, smem);
    } else {
        run_family<3, EPT3B>(x, es, as, W1_s, b1_s, W2_s, b2_s, out, ES, b - B2 - B3, BS, smem);
    }
}

extern "C" void kernel_launch(void* const* d_in, const int* in_sizes, int n_in,
                              void* d_out, int out_size)
{
    const float* x   = (const float*)d_in[0];
    const int*   e2  = (const int*)  d_in[1];
    const int*   e3  = (const int*)  d_in[2];
    const int*   es  = (const int*)  d_in[3];
    const float* a2  = (const float*)d_in[5];
    const float* a3  = (const float*)d_in[6];
    const float* as  = (const float*)d_in[7];
    const float* W1_2b = (const float*)d_in[9];
    const float* b1_2b = (const float*)d_in[10];
    const float* W2_2b = (const float*)d_in[11];
    const float* b2_2b = (const float*)d_in[12];
    const float* W1_3b = (const float*)d_in[13];
    const float* b1_3b = (const float*)d_in[14];
    const float* W2_3b = (const float*)d_in[15];
    const float* b2_3b = (const float*)d_in[16];
    const float* W1_s  = (const float*)d_in[17];
    const float* b1_s  = (const float*)d_in[18];
    const float* W2_s  = (const float*)d_in[19];
    const float* b2_s  = (const float*)d_in[20];

    const int E2 = in_sizes[1] / 2;
    const int E3 = in_sizes[2] / 3;
    const int ES = in_sizes[3] / 2;

    float* out = (float*)d_out;

    zero_kernel<<<(out_size + 255) / 256, 256>>>(out, out_size);

    constexpr int BLK = 128;
    const int B2 = (E2 + EPT3B * BLK - 1) / (EPT3B * BLK);
    const int B3 = (E3 + EPT6B * BLK - 1) / (EPT6B * BLK);
    const int BS = (ES + EPT3B * BLK - 1) / (EPT3B * BLK);

    fused_hignn_kernel<<<B2 + B3 + BS, BLK>>>(
        x,
        e2, a2, W1_2b, b1_2b, W2_2b, b2_2b,
        e3, a3, W1_3b, b1_3b, W2_3b, b2_3b,
        es, as, W1_s, b1_s, W2_s, b2_s,
        out, E2, E3, ES, B2, B3, BS);
}